// round 7
// baseline (speedup 1.0000x reference)
#include <cuda_runtime.h>
#include <math.h>

// B=64, C=64, H=W=128, M1=M2=32. BC = 4096 images.
// Reference (einsum labels as written): z = D X D^T ; corners mixed ; out = D z_out D^T.
// Decomposition: out = E X E^T + D Delta D^T,  E = D@D,  Delta corner-supported.

__device__ float g_D [128 * 128];        // DCT-II orthonormal matrix D[k][n]
__device__ float g_ET[128 * 128];        // E^T  (g_ET[a][b] = E[b][a])
__device__ float g_ZcT[2048u * 4096u];   // [kl][bc] corner coeffs / delta (33.5 MB)
__device__ float g_tmpBC[4096u * 2048u]; // [bc][kl] scratch (33.5 MB)
__device__ float g_WT[1024u * 4096u];    // [xy][o*64+i] transposed weights (16.8 MB)

// ---------------------------------------------------------------------------
__global__ void k_initD() {
    int idx = blockIdx.x * 256 + threadIdx.x;          // 16384
    int k = idx >> 7, n = idx & 127;
    double s = (k == 0) ? 0.08838834764831845 : 0.125;
    g_D[idx] = (float)(s * cospi((double)((2 * n + 1) * k) / 256.0));
}

// g_ET[a][b] = E[b][a] = sum_t D[b][t] * D[t][a]
__global__ void k_initE() {
    int a = blockIdx.x, b = threadIdx.x;               // 128 x 128
    double acc = 0.0;
    for (int t = 0; t < 128; t++)
        acc += (double)g_D[b * 128 + t] * (double)g_D[t * 128 + a];
    g_ET[a * 128 + b] = (float)acc;
}

// ---------------------------------------------------------------------------
// Transpose weights: W[(o*64+i)][xy] (4096 x 1024) -> g_WT[xy][o*64+i]
__global__ void k_transW(const float* __restrict__ in) {
    __shared__ float tile[32][33];
    const int c0 = blockIdx.x * 32, r0 = blockIdx.y * 32;
    const int tx = threadIdx.x, ty = threadIdx.y;      // (32, 8)
#pragma unroll
    for (int j = 0; j < 32; j += 8)
        tile[ty + j][tx] = in[(size_t)(r0 + ty + j) * 1024 + c0 + tx];
    __syncthreads();
#pragma unroll
    for (int j = 0; j < 32; j += 8)
        g_WT[(size_t)(c0 + ty + j) * 4096 + r0 + tx] = tile[tx][ty + j];
}

__global__ void k_transT1() {  // g_tmpBC [4096][2048] -> g_ZcT [2048][4096]
    __shared__ float tile[32][33];
    const int c0 = blockIdx.x * 32, r0 = blockIdx.y * 32;
    const int tx = threadIdx.x, ty = threadIdx.y;
#pragma unroll
    for (int j = 0; j < 32; j += 8)
        tile[ty + j][tx] = g_tmpBC[(size_t)(r0 + ty + j) * 2048 + c0 + tx];
    __syncthreads();
#pragma unroll
    for (int j = 0; j < 32; j += 8)
        g_ZcT[(size_t)(c0 + ty + j) * 4096 + r0 + tx] = tile[tx][ty + j];
}

__global__ void k_transT2() {  // g_ZcT [2048][4096] -> g_tmpBC [4096][2048]
    __shared__ float tile[32][33];
    const int c0 = blockIdx.x * 32, r0 = blockIdx.y * 32;
    const int tx = threadIdx.x, ty = threadIdx.y;
#pragma unroll
    for (int j = 0; j < 32; j += 8)
        tile[ty + j][tx] = g_ZcT[(size_t)(r0 + ty + j) * 4096 + c0 + tx];
    __syncthreads();
#pragma unroll
    for (int j = 0; j < 32; j += 8)
        g_tmpBC[(size_t)(c0 + ty + j) * 2048 + r0 + tx] = tile[tx][ty + j];
}

// ---------------------------------------------------------------------------
// Forward corner DCT: z_c = corner rows/cols of D X D^T.  One block per image.
// smem: Ds[64][129] + V[128][33] + xch[128][33] = 66816 B
__global__ void __launch_bounds__(256) k_fwd(const float* __restrict__ x) {
    extern __shared__ float sm[];
    float* Ds  = sm;
    float* V   = sm + 64 * 129;
    float* xch = sm + 64 * 129 + 128 * 33;
    const int t  = threadIdx.x;
    const int bc = blockIdx.x;
    const float4* ximg4 = (const float4*)(x + (size_t)bc * 16384);

    for (int i = t; i < 64 * 128; i += 256) {
        int ks = i >> 7, m = i & 127;
        int k = (ks < 32) ? ks : (64 + ks);
        Ds[ks * 129 + m] = g_D[k * 128 + m];
    }

    const int m0 = (t >> 3) * 4;
    const int l0 = (t & 7) * 4;
    float acc[4][4] = {};
    for (int nc = 0; nc < 4; nc++) {
        __syncthreads();
        for (int f = t; f < 1024; f += 256) {
            int m = f >> 3, j4 = f & 7;
            float4 v = ximg4[m * 32 + nc * 8 + j4];
            float* dst = xch + m * 33 + j4 * 4;
            dst[0] = v.x; dst[1] = v.y; dst[2] = v.z; dst[3] = v.w;
        }
        __syncthreads();
#pragma unroll 4
        for (int j = 0; j < 32; j++) {
            const int n = nc * 32 + j;
            float xv[4], dv[4];
#pragma unroll
            for (int i = 0; i < 4; i++) xv[i] = xch[(m0 + i) * 33 + j];
#pragma unroll
            for (int c = 0; c < 4; c++) dv[c] = Ds[(l0 + c) * 129 + n];
#pragma unroll
            for (int i = 0; i < 4; i++)
#pragma unroll
                for (int c = 0; c < 4; c++) acc[i][c] = fmaf(xv[i], dv[c], acc[i][c]);
        }
    }
#pragma unroll
    for (int i = 0; i < 4; i++)
#pragma unroll
        for (int c = 0; c < 4; c++) V[(m0 + i) * 33 + l0 + c] = acc[i][c];
    __syncthreads();

    const int ks0 = (t >> 3) * 2;
    float a2[2][4] = {};
#pragma unroll 4
    for (int m = 0; m < 128; m++) {
        float av[2], vv[4];
        av[0] = Ds[ks0 * 129 + m];
        av[1] = Ds[(ks0 + 1) * 129 + m];
#pragma unroll
        for (int c = 0; c < 4; c++) vv[c] = V[m * 33 + l0 + c];
#pragma unroll
        for (int i = 0; i < 2; i++)
#pragma unroll
            for (int c = 0; c < 4; c++) a2[i][c] = fmaf(av[i], vv[c], a2[i][c]);
    }
#pragma unroll
    for (int i = 0; i < 2; i++)
#pragma unroll
        for (int c = 0; c < 4; c++) xch[(ks0 + i) * 33 + l0 + c] = a2[i][c];
    __syncthreads();
    float* outp = g_tmpBC + (size_t)bc * 2048;
    for (int i = t; i < 2048; i += 256) outp[i] = xch[(i >> 5) * 33 + (i & 31)];
}

// ---------------------------------------------------------------------------
// Channel mixing: delta[b][o] = sum_i z[b][i]*w[o][i] - z[b][o], in place on g_ZcT.
__global__ void __launch_bounds__(256) k_mix() {
    __shared__ float Zs[64 * 65];
    __shared__ float Ws[64 * 65];
    const int kl = blockIdx.x, t = threadIdx.x;
    const int klw = ((kl >> 5) & 31) * 32 + (kl & 31);
    const float4* zin4 = (const float4*)(g_ZcT + (size_t)kl * 4096);
    const float4* win4 = (const float4*)(g_WT + (size_t)klw * 4096);
    for (int i = t; i < 1024; i += 256) {
        int r = i >> 4, c4 = (i & 15) * 4;
        float4 zv = zin4[i];
        float4 wv = win4[i];
        float* zd = Zs + r * 65 + c4;
        float* wd = Ws + r * 65 + c4;
        zd[0] = zv.x; zd[1] = zv.y; zd[2] = zv.z; zd[3] = zv.w;
        wd[0] = wv.x; wd[1] = wv.y; wd[2] = wv.z; wd[3] = wv.w;
    }
    __syncthreads();
    const int b0 = (t >> 4) * 4, o0 = (t & 15) * 4;
    float acc[4][4] = {};
#pragma unroll 4
    for (int i = 0; i < 64; i++) {
        float zb[4], wo[4];
#pragma unroll
        for (int a = 0; a < 4; a++) zb[a] = Zs[(b0 + a) * 65 + i];
#pragma unroll
        for (int c = 0; c < 4; c++) wo[c] = Ws[(o0 + c) * 65 + i];
#pragma unroll
        for (int a = 0; a < 4; a++)
#pragma unroll
            for (int c = 0; c < 4; c++) acc[a][c] = fmaf(zb[a], wo[c], acc[a][c]);
    }
#pragma unroll
    for (int a = 0; a < 4; a++)
#pragma unroll
        for (int c = 0; c < 4; c++) acc[a][c] -= Zs[(b0 + a) * 65 + o0 + c];
    __syncthreads();
#pragma unroll
    for (int a = 0; a < 4; a++)
#pragma unroll
        for (int c = 0; c < 4; c++) Ws[(b0 + a) * 64 + o0 + c] = acc[a][c];
    __syncthreads();
    float* zout = g_ZcT + (size_t)kl * 4096;
    for (int i = t; i < 2048; i += 256)
        ((float2*)zout)[i] = ((float2*)Ws)[i];
}

// ---------------------------------------------------------------------------
// Fused dense path, one block per image:
//   T1[m][l]  = sum_n X[m][n] * E[l][n]            (E[l][n] = g_ET[n][l])
//   P[m][l]   = sum_ks D[m][k(ks)] * Delta[ks][l]
//   out[m][n] = sum_j E[m][j]*T1[j][n] + sum_l P[m][l]*D[n][l]
// T1 never touches DRAM: it overwrites Xs in shared memory.
// smem (words): Xs 128*132 | Es 128*132 | Dcs 64*132 | dlt 32*132 | dels 64*36 | Ps 128*36
// total 53376 words = 213504 B
__global__ void __launch_bounds__(256) k_main(const float* __restrict__ x,
                                              float* __restrict__ out) {
    extern __shared__ float sm[];
    float* Xs   = sm;                    // [128][132]  X, then T1
    float* Es   = Xs  + 128 * 132;       // [128][132]  row a: g_ET[a][.]  (= E[.][a])
    float* Dcs  = Es  + 128 * 132;       // [64][132]   Dcs[ks][m] = D[m][k(ks)]
    float* dlt  = Dcs + 64 * 132;        // [32][132]   dlt[l][n]  = D[n][l]
    float* dels = dlt + 32 * 132;        // [64][36]    Delta[ks][l]
    float* Ps   = dels + 64 * 36;        // [128][36]
    const int t  = threadIdx.x;
    const int bc = blockIdx.x;

    const float4* ximg4 = (const float4*)(x + (size_t)bc * 16384);
    const float4* et4   = (const float4*)g_ET;
    for (int i4 = t; i4 < 4096; i4 += 256) {
        int r = i4 >> 5, c = i4 & 31;
        *((float4*)(Xs + r * 132) + c) = ximg4[i4];
        *((float4*)(Es + r * 132) + c) = et4[i4];
    }
    for (int i = t; i < 8192; i += 256) {
        int ks = i >> 7, m = i & 127;
        int k = (ks < 32) ? ks : (64 + ks);
        Dcs[ks * 132 + m] = g_D[m * 128 + k];
    }
    for (int i = t; i < 4096; i += 256) {
        int l = i >> 7, n = i & 127;
        dlt[l * 132 + n] = g_D[n * 128 + l];
    }
    {
        const float* din = g_tmpBC + (size_t)bc * 2048;
        for (int i = t; i < 2048; i += 256)
            dels[(i >> 5) * 36 + (i & 31)] = din[i];
    }
    __syncthreads();

    // P stage: 128x32, reduce 64.  4x4 tiles.
    {
        const int m0 = (t >> 3) * 4, l0 = (t & 7) * 4;
        float pa[4][4] = {};
#pragma unroll 4
        for (int ks = 0; ks < 64; ks++) {
            float4 a = *(const float4*)(Dcs + ks * 132 + m0);
            float4 b = *(const float4*)(dels + ks * 36 + l0);
            float av[4] = {a.x, a.y, a.z, a.w};
            float bv[4] = {b.x, b.y, b.z, b.w};
#pragma unroll
            for (int i = 0; i < 4; i++)
#pragma unroll
                for (int c = 0; c < 4; c++) pa[i][c] = fmaf(av[i], bv[c], pa[i][c]);
        }
#pragma unroll
        for (int i = 0; i < 4; i++)
#pragma unroll
            for (int c = 0; c < 4; c++) Ps[(m0 + i) * 36 + l0 + c] = pa[i][c];
    }

    // T1 stage: T1[m][l] = sum_n Xs[m][n] * Es[n][l].  Rows m = tm+16*i, cols l = tl*8+c.
    const int tm = t & 15, tl = t >> 4;
    float a1[8][8] = {};
    for (int n = 0; n < 128; n++) {
        float xv[8];
#pragma unroll
        for (int i = 0; i < 8; i++) xv[i] = Xs[(tm + 16 * i) * 132 + n];
        float4 ea = *(const float4*)(Es + n * 132 + tl * 8);
        float4 eb = *(const float4*)(Es + n * 132 + tl * 8 + 4);
        float ev[8] = {ea.x, ea.y, ea.z, ea.w, eb.x, eb.y, eb.z, eb.w};
#pragma unroll
        for (int i = 0; i < 8; i++)
#pragma unroll
            for (int c = 0; c < 8; c++) a1[i][c] = fmaf(xv[i], ev[c], a1[i][c]);
    }
    __syncthreads();                       // everyone done reading X; Ps complete
#pragma unroll
    for (int i = 0; i < 8; i++) {          // overwrite Xs with T1
        float* row = Xs + (tm + 16 * i) * 132 + tl * 8;
        float4 o1 = {a1[i][0], a1[i][1], a1[i][2], a1[i][3]};
        float4 o2 = {a1[i][4], a1[i][5], a1[i][6], a1[i][7]};
        *(float4*)(row)     = o1;
        *(float4*)(row + 4) = o2;
    }
    __syncthreads();

    // Out stage: out[m][n] = sum_j Es[j][m]*T1[j][n] (+ correction).
    // Rows m = tm+16*i, cols n = tl*8+c.
    float acc[8][8] = {};
    for (int j = 0; j < 128; j++) {
        float ev[8];
#pragma unroll
        for (int i = 0; i < 8; i++) ev[i] = Es[j * 132 + tm + 16 * i];
        float4 ta = *(const float4*)(Xs + j * 132 + tl * 8);
        float4 tb = *(const float4*)(Xs + j * 132 + tl * 8 + 4);
        float tv[8] = {ta.x, ta.y, ta.z, ta.w, tb.x, tb.y, tb.z, tb.w};
#pragma unroll
        for (int i = 0; i < 8; i++)
#pragma unroll
            for (int c = 0; c < 8; c++) acc[i][c] = fmaf(ev[i], tv[c], acc[i][c]);
    }
    for (int l = 0; l < 32; l++) {
        float pv[8];
#pragma unroll
        for (int i = 0; i < 8; i++) pv[i] = Ps[(tm + 16 * i) * 36 + l];
        float4 da = *(const float4*)(dlt + l * 132 + tl * 8);
        float4 db = *(const float4*)(dlt + l * 132 + tl * 8 + 4);
        float dv[8] = {da.x, da.y, da.z, da.w, db.x, db.y, db.z, db.w};
#pragma unroll
        for (int i = 0; i < 8; i++)
#pragma unroll
            for (int c = 0; c < 8; c++) acc[i][c] = fmaf(pv[i], dv[c], acc[i][c]);
    }
    float* op = out + (size_t)bc * 16384;
#pragma unroll
    for (int i = 0; i < 8; i++) {
        int row = tm + 16 * i;
        float4 o1 = {acc[i][0], acc[i][1], acc[i][2], acc[i][3]};
        float4 o2 = {acc[i][4], acc[i][5], acc[i][6], acc[i][7]};
        *(float4*)(op + row * 128 + tl * 8)     = o1;
        *(float4*)(op + row * 128 + tl * 8 + 4) = o2;
    }
}

// ---------------------------------------------------------------------------
extern "C" void kernel_launch(void* const* d_in, const int* in_sizes, int n_in,
                              void* d_out, int out_size) {
    const float* x = (const float*)d_in[0];
    const float* w = (const float*)d_in[1];
    if (n_in >= 2 && in_sizes[0] < in_sizes[1]) {
        const float* tmp = x; x = w; w = tmp;
    }
    float* out = (float*)d_out;

    cudaFuncSetAttribute(k_fwd,  cudaFuncAttributeMaxDynamicSharedMemorySize, 66816);
    cudaFuncSetAttribute(k_main, cudaFuncAttributeMaxDynamicSharedMemorySize, 213504);

    k_initD<<<64, 256>>>();
    k_initE<<<128, 128>>>();
    k_transW<<<dim3(32, 128), dim3(32, 8)>>>(w);
    k_fwd<<<4096, 256, 66816>>>(x);                   // corner z -> g_tmpBC
    k_transT1<<<dim3(64, 128), dim3(32, 8)>>>();      // -> g_ZcT [kl][bc]
    k_mix<<<2048, 256>>>();                           // delta in place
    k_transT2<<<dim3(128, 64), dim3(32, 8)>>>();      // -> g_tmpBC [bc][kl]
    k_main<<<4096, 256, 213504>>>(x, out);            // out = E X E^T + D Delta D^T
}